// round 2
// baseline (speedup 1.0000x reference)
#include <cuda_runtime.h>

// ---------------------------------------------------------------------------
// Problem constants
// ---------------------------------------------------------------------------
constexpr int CCH   = 66;     // channels
constexpr int TLEN  = 96;     // temporal length
constexpr int BSZ   = 2048;   // batch
constexpr int FIN   = 9 * CCH * 12;   // 7128
constexpr int HID   = 1936;
constexpr int NCLS  = 14;

// Scratch (no cudaMalloc allowed)
__device__ float g_feat[(size_t)BSZ * FIN];   // (2048, 7128)
__device__ float g_h[(size_t)BSZ * HID];      // (2048, 1936)

// ---------------------------------------------------------------------------
// Feature extraction: one 64-thread block per (batch, channel)
// ---------------------------------------------------------------------------
template<int K, int PAD>
__device__ __forceinline__ void run_branch(
    const float* __restrict__ xs,   // smem [96]
    float* hs,                      // smem [8*48]
    float* z1,                      // smem [4*24]
    const float* ws,  const float* bs,    // shared conv  (8*K), (8)
    const float* wi1, const float* bi1,   // grouped conv1 (4*8*K), (4)
    const float* wi2, const float* bi2,   // grouped conv2 (4*4*K), (4)
    float* feat_out, int slot_base, int tid)
{
    // ---- stage 1: shared conv (1->8, len 96), relu, pool2 -> hs[8][48] ----
    for (int idx = tid; idx < 8 * 48; idx += 64) {
        int o = idx / 48, u = idx - o * 48;
        int t0 = 2 * u - PAD;
        float a0 = bs[o], a1 = bs[o];
        #pragma unroll
        for (int k = 0; k < K; k++) {
            float w = ws[o * K + k];
            int t = t0 + k;
            if (t >= 0 && t < 96)         a0 = fmaf(xs[t],     w, a0);
            if (t + 1 >= 0 && t + 1 < 96) a1 = fmaf(xs[t + 1], w, a1);
        }
        hs[o * 48 + u] = 0.5f * (fmaxf(a0, 0.f) + fmaxf(a1, 0.f));
    }
    __syncthreads();

    // ---- stage 2: grouped conv (8->4, len 48), relu, pool2 -> z1[4][24] ----
    for (int idx = tid; idx < 4 * 24; idx += 64) {
        int j = idx / 24, u = idx - j * 24;
        int t0 = 2 * u - PAD;
        float a0 = bi1[j], a1 = bi1[j];
        #pragma unroll
        for (int i = 0; i < 8; i++) {
            const float* wrow = wi1 + (j * 8 + i) * K;
            const float* hrow = hs + i * 48;
            #pragma unroll
            for (int k = 0; k < K; k++) {
                float w = wrow[k];
                int t = t0 + k;
                if (t >= 0 && t < 48)         a0 = fmaf(hrow[t],     w, a0);
                if (t + 1 >= 0 && t + 1 < 48) a1 = fmaf(hrow[t + 1], w, a1);
            }
        }
        z1[j * 24 + u] = 0.5f * (fmaxf(a0, 0.f) + fmaxf(a1, 0.f));
    }
    __syncthreads();

    // ---- stage 3: grouped conv (4->4, len 24), relu, pool2 -> feat slots ----
    for (int idx = tid; idx < 4 * 12; idx += 64) {
        int j = idx / 12, u = idx - j * 12;
        int t0 = 2 * u - PAD;
        float a0 = bi2[j], a1 = bi2[j];
        #pragma unroll
        for (int i = 0; i < 4; i++) {
            const float* wrow = wi2 + (j * 4 + i) * K;
            const float* zrow = z1 + i * 24;
            #pragma unroll
            for (int k = 0; k < K; k++) {
                float w = wrow[k];
                int t = t0 + k;
                if (t >= 0 && t < 24)         a0 = fmaf(zrow[t],     w, a0);
                if (t + 1 >= 0 && t + 1 < 24) a1 = fmaf(zrow[t + 1], w, a1);
            }
        }
        feat_out[(slot_base + j) * 12 + u] = 0.5f * (fmaxf(a0, 0.f) + fmaxf(a1, 0.f));
    }
    __syncthreads();
}

__global__ void __launch_bounds__(64) feat_kernel(
    const float* __restrict__ x,
    const float* __restrict__ w_hs, const float* __restrict__ b_hs,
    const float* __restrict__ w_ls, const float* __restrict__ b_ls,
    const float* __restrict__ w_hi1, const float* __restrict__ b_hi1,
    const float* __restrict__ w_hi2, const float* __restrict__ b_hi2,
    const float* __restrict__ w_li1, const float* __restrict__ b_li1,
    const float* __restrict__ w_li2, const float* __restrict__ b_li2)
{
    const int c = blockIdx.x;
    const int b = blockIdx.y;
    const int tid = threadIdx.x;

    __shared__ float xs[96];
    __shared__ float hs[8 * 48];
    __shared__ float z1[4 * 24];
    __shared__ float sw_h[8 * 7],       sw_l[8 * 3];
    __shared__ float swi1_h[4 * 8 * 7], swi2_h[4 * 4 * 7];
    __shared__ float swi1_l[4 * 8 * 3], swi2_l[4 * 4 * 3];
    __shared__ float sb_h[8], sb_l[8];
    __shared__ float sbi1_h[4], sbi2_h[4], sbi1_l[4], sbi2_l[4];

    // stage-in: x row for this channel + all per-channel weights
    for (int i = tid; i < 96; i += 64)  xs[i]     = x[((size_t)b * 96 + i) * CCH + c];
    for (int i = tid; i < 56; i += 64)  sw_h[i]   = w_hs[i];
    if (tid < 24)                       sw_l[tid] = w_ls[tid];
    if (tid < 8) { sb_h[tid] = b_hs[tid]; sb_l[tid] = b_ls[tid]; }
    for (int i = tid; i < 224; i += 64) swi1_h[i] = w_hi1[c * 224 + i];
    for (int i = tid; i < 112; i += 64) swi2_h[i] = w_hi2[c * 112 + i];
    for (int i = tid; i < 96;  i += 64) swi1_l[i] = w_li1[c * 96 + i];
    if (tid < 48)                       swi2_l[tid] = w_li2[c * 48 + tid];
    if (tid < 4) {
        sbi1_h[tid] = b_hi1[c * 4 + tid];
        sbi2_h[tid] = b_hi2[c * 4 + tid];
        sbi1_l[tid] = b_li1[c * 4 + tid];
        sbi2_l[tid] = b_li2[c * 4 + tid];
    }
    __syncthreads();

    float* fo = g_feat + (size_t)b * FIN + c * 108;

    // slot 0: original signal pooled 3x (mean over 8 consecutive samples)
    if (tid < 12) {
        float s = 0.f;
        #pragma unroll
        for (int k = 0; k < 8; k++) s += xs[tid * 8 + k];
        fo[tid] = s * 0.125f;
    }

    // slots 1..4: low branch (K=3, pad=1)
    run_branch<3, 1>(xs, hs, z1, sw_l, sb_l, swi1_l, sbi1_l, swi2_l, sbi2_l, fo, 1, tid);
    // slots 5..8: high branch (K=7, pad=3)
    run_branch<7, 3>(xs, hs, z1, sw_h, sb_h, swi1_h, sbi1_h, swi2_h, sbi2_h, fo, 5, tid);
}

// ---------------------------------------------------------------------------
// fc1: g_h = relu(g_feat @ W1^T + b1)     (2048x7128) x (1936x7128)^T
// 128x128x8 tile, 256 threads, 8x8 micro-tile (strided fragments, conflict-free)
// ---------------------------------------------------------------------------
__global__ void __launch_bounds__(256) fc1_kernel(
    const float* __restrict__ Bw,     // (1936, 7128) row-major
    const float* __restrict__ bias)   // (1936)
{
    constexpr int K = FIN;
    constexpr int N = HID;

    const int bm = blockIdx.y * 128;
    const int bn = blockIdx.x * 128;
    const int tid = threadIdx.x;

    __shared__ float As[8][128];
    __shared__ float Bs[8][128];

    const int lm = tid & 127;          // load row within tile
    const int lk = (tid >> 7) * 4;     // 0 or 4
    const int ty = tid >> 4;           // 0..15
    const int tx = tid & 15;           // 0..15

    const float* Aptr = g_feat + (size_t)(bm + lm) * K + lk;
    const int nrow = bn + lm;
    const bool nok = nrow < N;
    const float* Bptr = Bw + (size_t)nrow * K + lk;

    float acc[8][8];
    #pragma unroll
    for (int i = 0; i < 8; i++)
        #pragma unroll
        for (int j = 0; j < 8; j++) acc[i][j] = 0.f;

    for (int kt = 0; kt < K; kt += 8) {
        float4 av = *(const float4*)(Aptr + kt);
        float4 bv = nok ? *(const float4*)(Bptr + kt) : make_float4(0.f, 0.f, 0.f, 0.f);
        As[lk + 0][lm] = av.x; As[lk + 1][lm] = av.y;
        As[lk + 2][lm] = av.z; As[lk + 3][lm] = av.w;
        Bs[lk + 0][lm] = bv.x; Bs[lk + 1][lm] = bv.y;
        Bs[lk + 2][lm] = bv.z; Bs[lk + 3][lm] = bv.w;
        __syncthreads();

        #pragma unroll
        for (int k = 0; k < 8; k++) {
            float a[8], bb[8];
            #pragma unroll
            for (int i = 0; i < 8; i++) a[i]  = As[k][ty + i * 16];
            #pragma unroll
            for (int j = 0; j < 8; j++) bb[j] = Bs[k][tx + j * 16];
            #pragma unroll
            for (int i = 0; i < 8; i++)
                #pragma unroll
                for (int j = 0; j < 8; j++)
                    acc[i][j] = fmaf(a[i], bb[j], acc[i][j]);
        }
        __syncthreads();
    }

    // epilogue: bias + relu
    #pragma unroll
    for (int j = 0; j < 8; j++) {
        int gn = bn + tx + j * 16;
        if (gn >= N) continue;
        float bj = bias[gn];
        #pragma unroll
        for (int i = 0; i < 8; i++) {
            int gm = bm + ty + i * 16;
            g_h[(size_t)gm * N + gn] = fmaxf(acc[i][j] + bj, 0.f);
        }
    }
}

// ---------------------------------------------------------------------------
// fc2: out = g_h @ W2^T + b2.   One warp per (m, n).
// ---------------------------------------------------------------------------
__global__ void __launch_bounds__(NCLS * 32) fc2_kernel(
    const float* __restrict__ w2,     // (14, 1936)
    const float* __restrict__ b2,     // (14)
    float* __restrict__ out)          // (2048, 14)
{
    const int m    = blockIdx.x;
    const int n    = threadIdx.x >> 5;
    const int lane = threadIdx.x & 31;

    const float* hrow = g_h + (size_t)m * HID;
    const float* wrow = w2 + n * HID;
    float s = 0.f;
    for (int k = lane; k < HID; k += 32)
        s = fmaf(hrow[k], wrow[k], s);
    #pragma unroll
    for (int off = 16; off > 0; off >>= 1)
        s += __shfl_down_sync(0xffffffffu, s, off);
    if (lane == 0) out[m * NCLS + n] = s + b2[n];
}

// ---------------------------------------------------------------------------
// Entry point
// ---------------------------------------------------------------------------
extern "C" void kernel_launch(void* const* d_in, const int* in_sizes, int n_in,
                              void* d_out, int out_size)
{
    const float* x     = (const float*)d_in[0];
    const float* w_hs  = (const float*)d_in[1];
    const float* b_hs  = (const float*)d_in[2];
    const float* w_ls  = (const float*)d_in[3];
    const float* b_ls  = (const float*)d_in[4];
    const float* w_hi1 = (const float*)d_in[5];
    const float* b_hi1 = (const float*)d_in[6];
    const float* w_hi2 = (const float*)d_in[7];
    const float* b_hi2 = (const float*)d_in[8];
    const float* w_li1 = (const float*)d_in[9];
    const float* b_li1 = (const float*)d_in[10];
    const float* w_li2 = (const float*)d_in[11];
    const float* b_li2 = (const float*)d_in[12];
    const float* w_fc1 = (const float*)d_in[13];
    const float* b_fc1 = (const float*)d_in[14];
    const float* w_fc2 = (const float*)d_in[15];
    const float* b_fc2 = (const float*)d_in[16];
    float* out = (float*)d_out;

    feat_kernel<<<dim3(CCH, BSZ), 64>>>(x, w_hs, b_hs, w_ls, b_ls,
                                        w_hi1, b_hi1, w_hi2, b_hi2,
                                        w_li1, b_li1, w_li2, b_li2);
    fc1_kernel<<<dim3(16, 16), 256>>>(w_fc1, b_fc1);
    fc2_kernel<<<BSZ, NCLS * 32>>>(w_fc2, b_fc2, out);
}

// round 4
// speedup vs baseline: 2.8396x; 2.8396x over previous
#include <cuda_runtime.h>
#include <cuda_bf16.h>
#include <cstdint>

// ---------------------------------------------------------------------------
// Problem constants
// ---------------------------------------------------------------------------
constexpr int CCH   = 66;
constexpr int TLEN  = 96;
constexpr int BSZ   = 2048;
constexpr int FIN   = 9 * CCH * 12;   // 7128
constexpr int HID   = 1936;
constexpr int NCLS  = 14;

// fc1 GEMM padded dims (split-precision bf16: A'=[Ahi|Ahi|Alo], B'=[Bhi|Blo|Bhi])
constexpr int KSEC  = 7168;           // 7128 -> 64-multiple
constexpr int KP    = 3 * KSEC;       // 21504
constexpr int NPAD  = 2048;
constexpr int KT    = KP / 32;        // 672 k-steps of 32

// ---------------------------------------------------------------------------
// Scratch (static __device__)
// ---------------------------------------------------------------------------
__device__ __align__(16) float g_xt[(size_t)BSZ * CCH * TLEN];
__device__ __align__(16) float g_feat[(size_t)BSZ * FIN];
__device__ __align__(16) float g_h[(size_t)BSZ * HID];
__device__ __align__(16) __nv_bfloat16 g_A2[(size_t)BSZ * KP];
__device__ __align__(16) __nv_bfloat16 g_B2[(size_t)NPAD * KP];

// ---------------------------------------------------------------------------
// PTX helpers (portable: cp.async + ldmatrix + mma.sync, all sm_80+)
// ---------------------------------------------------------------------------
__device__ __forceinline__ uint32_t smem_to_u32(const void* p) {
    uint32_t a;
    asm("{ .reg .u64 t; cvta.to.shared.u64 t, %1; cvt.u32.u64 %0, t; }" : "=r"(a) : "l"(p));
    return a;
}
__device__ __forceinline__ void cp16(uint32_t dst, const void* src) {
    asm volatile("cp.async.cg.shared.global [%0], [%1], 16;" :: "r"(dst), "l"(src));
}
#define CP_COMMIT() asm volatile("cp.async.commit_group;" ::: "memory")
#define CP_WAIT2()  asm volatile("cp.async.wait_group 2;" ::: "memory")

__device__ __forceinline__ void ldsm_x4(uint32_t* r, uint32_t addr) {
    asm volatile("ldmatrix.sync.aligned.m8n8.x4.shared.b16 {%0,%1,%2,%3}, [%4];"
                 : "=r"(r[0]), "=r"(r[1]), "=r"(r[2]), "=r"(r[3]) : "r"(addr));
}
__device__ __forceinline__ void mma16816(float* d, const uint32_t* a,
                                         uint32_t b0, uint32_t b1) {
    asm volatile(
        "mma.sync.aligned.m16n8k16.row.col.f32.bf16.bf16.f32 "
        "{%0,%1,%2,%3}, {%4,%5,%6,%7}, {%8,%9}, {%0,%1,%2,%3};"
        : "+f"(d[0]), "+f"(d[1]), "+f"(d[2]), "+f"(d[3])
        : "r"(a[0]), "r"(a[1]), "r"(a[2]), "r"(a[3]), "r"(b0), "r"(b1));
}

// ---------------------------------------------------------------------------
// Transpose: x (B, T, C) -> g_xt (B, C, T)
// ---------------------------------------------------------------------------
__global__ void __launch_bounds__(256) transpose_kernel(const float* __restrict__ x) {
    __shared__ float s[TLEN * CCH];
    const int b = blockIdx.x;
    const float* src = x + (size_t)b * TLEN * CCH;
    for (int i = threadIdx.x; i < TLEN * CCH; i += 256) s[i] = src[i];
    __syncthreads();
    float* dst = g_xt + (size_t)b * CCH * TLEN;
    for (int i = threadIdx.x; i < TLEN * CCH; i += 256) {
        int c = i / TLEN, t = i - c * TLEN;
        dst[i] = s[t * CCH + c];
    }
}

// ---------------------------------------------------------------------------
// Feature extraction: one 64-thread block per (b, c).
// Padded SMEM halos -> no bounds predicates; windowed loads.
// ---------------------------------------------------------------------------
template<int K, int PAD>
__device__ __forceinline__ void run_branch(
    const float* xsp, float* hs, float* z1,
    const float* ws,  const float* bs,
    const float* wi1, const float* bi1,
    const float* wi2, const float* bi2,
    float* fo, int slot_base, int tid)
{
    {   // stage 1: shared conv 1->8 (96), relu, pool2 -> hs rows of 48
        const int o = tid >> 3, g = tid & 7;
        float wreg[K];
        #pragma unroll
        for (int k = 0; k < K; k++) wreg[k] = ws[o * K + k];
        const float bo = bs[o];
        float* hrow = hs + o * 56 + 4;
        #pragma unroll
        for (int ub = 0; ub < 48; ub += 8) {
            const int uu = ub + g;
            const int t0 = 2 * uu - PAD;
            float v[K + 1];
            #pragma unroll
            for (int j = 0; j <= K; j++) v[j] = xsp[t0 + j];
            float a0 = bo, a1 = bo;
            #pragma unroll
            for (int k = 0; k < K; k++) {
                a0 = fmaf(v[k],     wreg[k], a0);
                a1 = fmaf(v[k + 1], wreg[k], a1);
            }
            hrow[uu] = 0.5f * (fmaxf(a0, 0.f) + fmaxf(a1, 0.f));
        }
    }
    __syncthreads();
    {   // stage 2: grouped conv 8->4 (48), relu, pool2 -> z1 rows of 24
        const int j = tid >> 4, g = tid & 15;
        const float bj = bi1[j];
        const float* wbase = wi1 + j * 8 * K;
        for (int uu = g; uu < 24; uu += 16) {
            const int t0 = 2 * uu - PAD;
            float a0 = bj, a1 = bj;
            #pragma unroll
            for (int i = 0; i < 8; i++) {
                const float* hrow = hs + i * 56 + 4 + t0;
                const float* wr = wbase + i * K;
                float v[K + 1];
                #pragma unroll
                for (int jj = 0; jj <= K; jj++) v[jj] = hrow[jj];
                #pragma unroll
                for (int k = 0; k < K; k++) {
                    float w = wr[k];
                    a0 = fmaf(v[k],     w, a0);
                    a1 = fmaf(v[k + 1], w, a1);
                }
            }
            z1[j * 32 + 4 + uu] = 0.5f * (fmaxf(a0, 0.f) + fmaxf(a1, 0.f));
        }
    }
    __syncthreads();
    {   // stage 3: grouped conv 4->4 (24), relu, pool2 -> 12 outputs
        const int j = tid >> 4, g = tid & 15;
        if (g < 12) {
            const int uu = g;
            const int t0 = 2 * uu - PAD;
            float a0 = bi2[j], a1 = bi2[j];
            #pragma unroll
            for (int i = 0; i < 4; i++) {
                const float* zrow = z1 + i * 32 + 4 + t0;
                const float* wr = wi2 + (j * 4 + i) * K;
                float v[K + 1];
                #pragma unroll
                for (int jj = 0; jj <= K; jj++) v[jj] = zrow[jj];
                #pragma unroll
                for (int k = 0; k < K; k++) {
                    float w = wr[k];
                    a0 = fmaf(v[k],     w, a0);
                    a1 = fmaf(v[k + 1], w, a1);
                }
            }
            fo[(slot_base + j) * 12 + uu] = 0.5f * (fmaxf(a0, 0.f) + fmaxf(a1, 0.f));
        }
    }
    __syncthreads();
}

__global__ void __launch_bounds__(64) feat_kernel(
    const float* __restrict__ w_hs, const float* __restrict__ b_hs,
    const float* __restrict__ w_ls, const float* __restrict__ b_ls,
    const float* __restrict__ w_hi1, const float* __restrict__ b_hi1,
    const float* __restrict__ w_hi2, const float* __restrict__ b_hi2,
    const float* __restrict__ w_li1, const float* __restrict__ b_li1,
    const float* __restrict__ w_li2, const float* __restrict__ b_li2)
{
    const int c = blockIdx.x;
    const int b = blockIdx.y;
    const int tid = threadIdx.x;

    __shared__ float xs[104];
    __shared__ float hs[8 * 56];
    __shared__ float z1[4 * 32];
    __shared__ float sw_h[8 * 7],       sw_l[8 * 3];
    __shared__ float swi1_h[4 * 8 * 7], swi2_h[4 * 4 * 7];
    __shared__ float swi1_l[4 * 8 * 3], swi2_l[4 * 4 * 3];
    __shared__ float sb_h[8], sb_l[8];
    __shared__ float sbi1_h[4], sbi2_h[4], sbi1_l[4], sbi2_l[4];

    for (int i = tid; i < 8 * 56; i += 64) hs[i] = 0.f;
    for (int i = tid; i < 4 * 32; i += 64) z1[i] = 0.f;
    if (tid < 4) { xs[tid] = 0.f; xs[100 + tid] = 0.f; }

    const float* xrow = g_xt + ((size_t)b * CCH + c) * TLEN;
    for (int i = tid; i < 96; i += 64) xs[4 + i] = xrow[i];
    for (int i = tid; i < 56; i += 64) sw_h[i] = w_hs[i];
    if (tid < 24)                      sw_l[tid] = w_ls[tid];
    if (tid < 8) { sb_h[tid] = b_hs[tid]; sb_l[tid] = b_ls[tid]; }
    for (int i = tid; i < 224; i += 64) swi1_h[i] = w_hi1[c * 224 + i];
    for (int i = tid; i < 112; i += 64) swi2_h[i] = w_hi2[c * 112 + i];
    for (int i = tid; i < 96;  i += 64) swi1_l[i] = w_li1[c * 96 + i];
    if (tid < 48)                       swi2_l[tid] = w_li2[c * 48 + tid];
    if (tid < 4) {
        sbi1_h[tid] = b_hi1[c * 4 + tid];
        sbi2_h[tid] = b_hi2[c * 4 + tid];
        sbi1_l[tid] = b_li1[c * 4 + tid];
        sbi2_l[tid] = b_li2[c * 4 + tid];
    }
    __syncthreads();

    float* fo = g_feat + (size_t)b * FIN + c * 108;
    const float* xsp = xs + 4;

    if (tid < 12) {
        float s = 0.f;
        #pragma unroll
        for (int k = 0; k < 8; k++) s += xsp[tid * 8 + k];
        fo[tid] = s * 0.125f;
    }

    run_branch<3, 1>(xsp, hs, z1, sw_l, sb_l, swi1_l, sbi1_l, swi2_l, sbi2_l, fo, 1, tid);
    run_branch<7, 3>(xsp, hs, z1, sw_h, sb_h, swi1_h, sbi1_h, swi2_h, sbi2_h, fo, 5, tid);
}

// ---------------------------------------------------------------------------
// Split-precision conversion fp32 -> (hi, lo) bf16
// ---------------------------------------------------------------------------
__device__ __forceinline__ void split8(const float* v, __nv_bfloat16* hi, __nv_bfloat16* lo) {
    #pragma unroll
    for (int i = 0; i < 8; i++) {
        __nv_bfloat16 h = __float2bfloat16(v[i]);
        hi[i] = h;
        lo[i] = __float2bfloat16(v[i] - __bfloat162float(h));
    }
}

__global__ void __launch_bounds__(256) convA_kernel() {
    const size_t idx = (size_t)blockIdx.x * 256 + threadIdx.x;   // 2048*896
    const int m  = (int)(idx / 896);
    const int kb = (int)(idx % 896);
    const int k0 = kb * 8;
    float v[8];
    if (kb < 891) {
        float4 a = *(const float4*)(g_feat + (size_t)m * FIN + k0);
        float4 b = *(const float4*)(g_feat + (size_t)m * FIN + k0 + 4);
        v[0]=a.x; v[1]=a.y; v[2]=a.z; v[3]=a.w; v[4]=b.x; v[5]=b.y; v[6]=b.z; v[7]=b.w;
    } else {
        #pragma unroll
        for (int i = 0; i < 8; i++) v[i] = 0.f;
    }
    __align__(16) __nv_bfloat16 hi[8], lo[8];
    split8(v, hi, lo);
    __nv_bfloat16* dst = g_A2 + (size_t)m * KP + k0;
    *(uint4*)(dst)            = *(uint4*)hi;
    *(uint4*)(dst + KSEC)     = *(uint4*)hi;
    *(uint4*)(dst + 2 * KSEC) = *(uint4*)lo;
}

__global__ void __launch_bounds__(256) convB_kernel(const float* __restrict__ w1) {
    const size_t idx = (size_t)blockIdx.x * 256 + threadIdx.x;   // 2048*896
    const int n  = (int)(idx / 896);
    const int kb = (int)(idx % 896);
    const int k0 = kb * 8;
    float v[8];
    if (n < HID && kb < 891) {
        float4 a = *(const float4*)(w1 + (size_t)n * FIN + k0);
        float4 b = *(const float4*)(w1 + (size_t)n * FIN + k0 + 4);
        v[0]=a.x; v[1]=a.y; v[2]=a.z; v[3]=a.w; v[4]=b.x; v[5]=b.y; v[6]=b.z; v[7]=b.w;
    } else {
        #pragma unroll
        for (int i = 0; i < 8; i++) v[i] = 0.f;
    }
    __align__(16) __nv_bfloat16 hi[8], lo[8];
    split8(v, hi, lo);
    __nv_bfloat16* dst = g_B2 + (size_t)n * KP + k0;
    *(uint4*)(dst)            = *(uint4*)hi;
    *(uint4*)(dst + KSEC)     = *(uint4*)lo;
    *(uint4*)(dst + 2 * KSEC) = *(uint4*)hi;
}

// ---------------------------------------------------------------------------
// fc1 GEMM via mma.sync (HMMA bf16), 128x128x32 tile, 4-stage cp.async.
// C[m,n] = sum_k A2[m,k] * B2[n,k];  epilogue bias+relu -> g_h.
// SMEM per stage: A 128x32 bf16 (8KB) + B 128x32 bf16 (8KB).
// Chunk swizzle: 16B chunk cu of row r stored at r*64 + ((cu ^ ((r>>1)&3))*16).
// ---------------------------------------------------------------------------
constexpr int GSTAGES = 4;
constexpr int STAGE_BYTES = 16384;
constexpr int GSMEM_BYTES = GSTAGES * STAGE_BYTES;   // 64 KB

__global__ void __launch_bounds__(256) gemm_kernel(const float* __restrict__ bias) {
    extern __shared__ char smem[];
    const uint32_t smem_u32 = smem_to_u32(smem);
    const int tid  = threadIdx.x;
    const int wid  = tid >> 5;
    const int lane = tid & 31;
    const int bm = blockIdx.y * 128;
    const int bn = blockIdx.x * 128;

    const int warp_m = wid & 1;          // 2 -> 64 rows each
    const int warp_n = wid >> 1;         // 4 -> 32 cols each

    // ---- cp.async per-thread assignment: 4 lanes cover one 64B row-chunk run
    const int lcu  = tid & 3;            // 16B chunk within 64B k-slice
    const int lrow = tid >> 2;           // 0..63 ; rows lrow, lrow+64
    const __nv_bfloat16* srcA[2];
    const __nv_bfloat16* srcB[2];
    uint32_t dstA[2], dstB[2];
    #pragma unroll
    for (int i = 0; i < 2; i++) {
        const int r = lrow + 64 * i;
        srcA[i] = g_A2 + (size_t)(bm + r) * KP + lcu * 8;
        srcB[i] = g_B2 + (size_t)(bn + r) * KP + lcu * 8;
        const uint32_t sw = (uint32_t)((lcu ^ ((r >> 1) & 3)) << 4);
        dstA[i] = r * 64 + sw;
        dstB[i] = 8192 + r * 64 + sw;
    }

    // ---- ldmatrix per-thread smem offsets
    const int g8 = lane >> 3;            // ldmatrix group 0..3
    const int l8 = lane & 7;
    uint32_t aoff[8];                    // [mt][ks]
    #pragma unroll
    for (int mt = 0; mt < 4; mt++) {
        const int mrow = warp_m * 64 + mt * 16 + (g8 & 1) * 8 + l8;
        const int s = (mrow >> 1) & 3;
        #pragma unroll
        for (int ks = 0; ks < 2; ks++) {
            const int cu = 2 * ks + (g8 >> 1);
            aoff[mt * 2 + ks] = mrow * 64 + ((cu ^ s) << 4);
        }
    }
    uint32_t boff[4];                    // [p][ks], p = n-pair (16 cols)
    #pragma unroll
    for (int p = 0; p < 2; p++) {
        const int nrow = warp_n * 32 + p * 16 + (g8 >> 1) * 8 + l8;
        const int s = (nrow >> 1) & 3;
        #pragma unroll
        for (int ks = 0; ks < 2; ks++) {
            const int cu = 2 * ks + (g8 & 1);
            boff[p * 2 + ks] = 8192 + nrow * 64 + ((cu ^ s) << 4);
        }
    }

    float acc[4][4][4];
    #pragma unroll
    for (int mt = 0; mt < 4; mt++)
        #pragma unroll
        for (int nt = 0; nt < 4; nt++)
            #pragma unroll
            for (int e = 0; e < 4; e++) acc[mt][nt][e] = 0.f;

    // ---- prologue: fill 3 stages
    #pragma unroll
    for (int kt = 0; kt < GSTAGES - 1; kt++) {
        const uint32_t sb = smem_u32 + kt * STAGE_BYTES;
        #pragma unroll
        for (int i = 0; i < 2; i++) {
            cp16(sb + dstA[i], srcA[i] + (size_t)kt * 32);
            cp16(sb + dstB[i], srcB[i] + (size_t)kt * 32);
        }
        CP_COMMIT();
    }

    // ---- main loop
    for (int kt = 0; kt < KT; kt++) {
        CP_WAIT2();
        __syncthreads();

        const int knext = kt + GSTAGES - 1;
        if (knext < KT) {
            const uint32_t sb = smem_u32 + (knext & 3) * STAGE_BYTES;
            #pragma unroll
            for (int i = 0; i < 2; i++) {
                cp16(sb + dstA[i], srcA[i] + (size_t)knext * 32);
                cp16(sb + dstB[i], srcB[i] + (size_t)knext * 32);
            }
        }
        CP_COMMIT();

        const uint32_t sb = smem_u32 + (kt & 3) * STAGE_BYTES;
        #pragma unroll
        for (int ks = 0; ks < 2; ks++) {
            uint32_t afr[4][4], bfr[2][4];
            #pragma unroll
            for (int mt = 0; mt < 4; mt++) ldsm_x4(afr[mt], sb + aoff[mt * 2 + ks]);
            #pragma unroll
            for (int p = 0; p < 2; p++)    ldsm_x4(bfr[p],  sb + boff[p * 2 + ks]);
            #pragma unroll
            for (int mt = 0; mt < 4; mt++)
                #pragma unroll
                for (int nt = 0; nt < 4; nt++)
                    mma16816(acc[mt][nt], afr[mt],
                             bfr[nt >> 1][(nt & 1) * 2],
                             bfr[nt >> 1][(nt & 1) * 2 + 1]);
        }
    }

    // ---- epilogue: bias + relu -> g_h (n < HID)
    const int qrow = lane >> 2;          // 0..7
    const int qcol = (lane & 3) * 2;
    #pragma unroll
    for (int mt = 0; mt < 4; mt++) {
        #pragma unroll
        for (int nt = 0; nt < 4; nt++) {
            const int n = bn + warp_n * 32 + nt * 8 + qcol;
            if (n >= HID) continue;
            const float b0 = bias[n], b1 = bias[n + 1];
            #pragma unroll
            for (int half = 0; half < 2; half++) {
                const int m = bm + warp_m * 64 + mt * 16 + qrow + half * 8;
                float* o = g_h + (size_t)m * HID + n;
                o[0] = fmaxf(acc[mt][nt][half * 2 + 0] + b0, 0.f);
                o[1] = fmaxf(acc[mt][nt][half * 2 + 1] + b1, 0.f);
            }
        }
    }
}

// ---------------------------------------------------------------------------
// fc2: out = g_h @ W2^T + b2
// ---------------------------------------------------------------------------
__global__ void __launch_bounds__(NCLS * 32) fc2_kernel(
    const float* __restrict__ w2, const float* __restrict__ b2,
    float* __restrict__ out)
{
    const int m    = blockIdx.x;
    const int n    = threadIdx.x >> 5;
    const int lane = threadIdx.x & 31;
    const float* hrow = g_h + (size_t)m * HID;
    const float* wrow = w2 + n * HID;
    float s = 0.f;
    for (int k = lane; k < HID; k += 32)
        s = fmaf(hrow[k], wrow[k], s);
    #pragma unroll
    for (int off = 16; off > 0; off >>= 1)
        s += __shfl_down_sync(0xffffffffu, s, off);
    if (lane == 0) out[m * NCLS + n] = s + b2[n];
}

// ---------------------------------------------------------------------------
// Entry
// ---------------------------------------------------------------------------
extern "C" void kernel_launch(void* const* d_in, const int* in_sizes, int n_in,
                              void* d_out, int out_size)
{
    const float* x     = (const float*)d_in[0];
    const float* w_hs  = (const float*)d_in[1];
    const float* b_hs  = (const float*)d_in[2];
    const float* w_ls  = (const float*)d_in[3];
    const float* b_ls  = (const float*)d_in[4];
    const float* w_hi1 = (const float*)d_in[5];
    const float* b_hi1 = (const float*)d_in[6];
    const float* w_hi2 = (const float*)d_in[7];
    const float* b_hi2 = (const float*)d_in[8];
    const float* w_li1 = (const float*)d_in[9];
    const float* b_li1 = (const float*)d_in[10];
    const float* w_li2 = (const float*)d_in[11];
    const float* b_li2 = (const float*)d_in[12];
    const float* w_fc1 = (const float*)d_in[13];
    const float* b_fc1 = (const float*)d_in[14];
    const float* w_fc2 = (const float*)d_in[15];
    const float* b_fc2 = (const float*)d_in[16];
    float* out = (float*)d_out;

    static bool attr_set = false;
    if (!attr_set) {
        cudaFuncSetAttribute(gemm_kernel, cudaFuncAttributeMaxDynamicSharedMemorySize,
                             GSMEM_BYTES);
        attr_set = true;
    }

    transpose_kernel<<<BSZ, 256>>>(x);
    convB_kernel<<<(NPAD * 896) / 256, 256>>>(w_fc1);
    feat_kernel<<<dim3(CCH, BSZ), 64>>>(w_hs, b_hs, w_ls, b_ls,
                                        w_hi1, b_hi1, w_hi2, b_hi2,
                                        w_li1, b_li1, w_li2, b_li2);
    convA_kernel<<<(BSZ * 896) / 256, 256>>>();
    gemm_kernel<<<dim3(16, 16), 256, GSMEM_BYTES>>>(b_fc1);
    fc2_kernel<<<BSZ, NCLS * 32>>>(w_fc2, b_fc2, out);
}